// round 2
// baseline (speedup 1.0000x reference)
#include <cuda_runtime.h>

// Problem constants (fixed by reference setup_inputs)
#define S_DIM   2
#define B_DIM   8
#define N_DIM   2048
#define D_DIM   64
#define P_DIM   32
#define BLK_T   8      // time blocks
#define HID     256
#define NSTEPS  2      // RK4 steps per block

#define TN      16     // nodes per CTA
#define NTHREADS 256

#define CPAD    260    // row stride (floats) for c/h  (bank-shift 4)
#define XPAD    68     // row stride (floats) for x/y/k/bb (bank-shift 4)

// shared layout (floats)
//  sW1a : 64*256        = 16384
//  sW2  : 256*64        = 16384  (holds W1p rows 64..95 during init)
//  sC   : TN*CPAD       = 4160
//  sH   : TN*CPAD       = 4160   (also GEMM2 partial scratch, 4096 used)
//  sX,sY,sK,sBB : 4 * TN*XPAD = 4352
//  sPhi : TN*32         = 512
//  sB1  : 256
//  sDel : 8
#define SMEM_FLOATS (16384 + 16384 + 4160 + 4160 + 4*(TN*XPAD) + 512 + 256 + 8)

__device__ __forceinline__ float comp4(const float4 v, int j) {
    return j == 0 ? v.x : (j == 1 ? v.y : (j == 2 ? v.z : v.w));
}

extern __shared__ float smem[];

__device__ __forceinline__ void dyn_eval(
    const float* __restrict__ sIn,   // [TN][XPAD] input state
    float* __restrict__ sH,          // [TN][CPAD] hidden / partial scratch
    const float* __restrict__ sW1a,  // [64][256]
    const float* __restrict__ sC,    // [TN][CPAD]
    const float* __restrict__ sW2,   // [256][64]
    const float* __restrict__ sBB,   // [TN][XPAD]  (b + b2)
    float* __restrict__ sK,          // [TN][XPAD] output k
    float dlt, int tid)
{
    // ---------------- GEMM1: h = tanh(in @ W1a + c) ----------------
    {
        const int nb = (tid >> 6) * 4;       // 4 node groups
        const int hc = (tid & 63) * 4;       // 64 hidden-col groups of 4
        float acc[4][4];
        #pragma unroll
        for (int nr = 0; nr < 4; nr++) {
            float4 cv = *(const float4*)(sC + (nb + nr) * CPAD + hc);
            acc[nr][0] = cv.x; acc[nr][1] = cv.y; acc[nr][2] = cv.z; acc[nr][3] = cv.w;
        }
        #pragma unroll 4
        for (int f = 0; f < D_DIM; f += 4) {
            float4 yv[4];
            #pragma unroll
            for (int nr = 0; nr < 4; nr++)
                yv[nr] = *(const float4*)(sIn + (nb + nr) * XPAD + f);
            #pragma unroll
            for (int j = 0; j < 4; j++) {
                float4 wv = *(const float4*)(sW1a + (f + j) * HID + hc);
                #pragma unroll
                for (int nr = 0; nr < 4; nr++) {
                    float y = comp4(yv[nr], j);
                    acc[nr][0] += y * wv.x; acc[nr][1] += y * wv.y;
                    acc[nr][2] += y * wv.z; acc[nr][3] += y * wv.w;
                }
            }
        }
        #pragma unroll
        for (int nr = 0; nr < 4; nr++) {
            float4 hv;
            hv.x = tanhf(acc[nr][0]); hv.y = tanhf(acc[nr][1]);
            hv.z = tanhf(acc[nr][2]); hv.w = tanhf(acc[nr][3]);
            *(float4*)(sH + (nb + nr) * CPAD + hc) = hv;
        }
    }
    __syncthreads();

    // ---------------- GEMM2: k = (h @ W2 + bb) * dlt ----------------
    // split-K: 4 hh-slices of 64, 4x4 register tiles, reduce through sH scratch
    float pacc[4][4];
    const int hs = tid >> 6;            // 4 hh slices
    const int ng = (tid >> 4) & 3;      // 4 node groups
    const int dg = tid & 15;            // 16 d-col groups
    {
        const int nb  = ng * 4;
        const int dc  = dg * 4;
        const int hh0 = hs * 64;
        #pragma unroll
        for (int nr = 0; nr < 4; nr++)
            pacc[nr][0] = pacc[nr][1] = pacc[nr][2] = pacc[nr][3] = 0.f;
        #pragma unroll 4
        for (int hh = 0; hh < 64; hh += 4) {
            float4 hv[4];
            #pragma unroll
            for (int nr = 0; nr < 4; nr++)
                hv[nr] = *(const float4*)(sH + (nb + nr) * CPAD + hh0 + hh);
            #pragma unroll
            for (int j = 0; j < 4; j++) {
                float4 wv = *(const float4*)(sW2 + (hh0 + hh + j) * D_DIM + dc);
                #pragma unroll
                for (int nr = 0; nr < 4; nr++) {
                    float h = comp4(hv[nr], j);
                    pacc[nr][0] += h * wv.x; pacc[nr][1] += h * wv.y;
                    pacc[nr][2] += h * wv.z; pacc[nr][3] += h * wv.w;
                }
            }
        }
    }
    __syncthreads();   // sH reads done; reuse as partial scratch
    {
        const int nb = ng * 4;
        const int dc = dg * 4;
        #pragma unroll
        for (int nr = 0; nr < 4; nr++) {
            float4 pv = make_float4(pacc[nr][0], pacc[nr][1], pacc[nr][2], pacc[nr][3]);
            *(float4*)(sH + hs * 1024 + (nb + nr) * D_DIM + dc) = pv;
        }
    }
    __syncthreads();
    {
        // thread reduces outputs [tid*4 .. tid*4+3]
        const int node = tid >> 4;
        const int col  = (tid & 15) * 4;
        float4 a = *(const float4*)(sH + 0 * 1024 + tid * 4);
        #pragma unroll
        for (int p = 1; p < 4; p++) {
            float4 b = *(const float4*)(sH + p * 1024 + tid * 4);
            a.x += b.x; a.y += b.y; a.z += b.z; a.w += b.w;
        }
        float4 bbv = *(const float4*)(sBB + node * XPAD + col);
        float4 kv;
        kv.x = (a.x + bbv.x) * dlt; kv.y = (a.y + bbv.y) * dlt;
        kv.z = (a.z + bbv.z) * dlt; kv.w = (a.w + bbv.w) * dlt;
        *(float4*)(sK + node * XPAD + col) = kv;
    }
    __syncthreads();
}

__global__ __launch_bounds__(NTHREADS, 1)
void ode_fused_kernel(const float* __restrict__ gS,  const float* __restrict__ gT,
                      const float* __restrict__ gPhi, const float* __restrict__ gB,
                      const float* __restrict__ gW1, const float* __restrict__ gb1,
                      const float* __restrict__ gW2, const float* __restrict__ gb2,
                      float* __restrict__ gOut)
{
    float* sW1a = smem;                       // 16384
    float* sW2  = sW1a + 16384;               // 16384 (W1p during init)
    float* sC   = sW2  + 16384;               // TN*CPAD
    float* sH   = sC   + TN * CPAD;           // TN*CPAD
    float* sX   = sH   + TN * CPAD;           // TN*XPAD
    float* sY   = sX   + TN * XPAD;
    float* sK   = sY   + TN * XPAD;
    float* sBB  = sK   + TN * XPAD;
    float* sPhi = sBB  + TN * XPAD;           // TN*32
    float* sB1  = sPhi + TN * 32;             // 256
    float* sDel = sB1  + 256;                 // 8

    const int tid   = threadIdx.x;
    const int sb    = blockIdx.x >> 7;        // 16 (s,b) pairs
    const int tile  = blockIdx.x & 127;       // 128 tiles of TN nodes
    const int node0 = tile * TN;
    const int s_i   = sb >> 3;
    const int b_i   = sb & 7;

    // ---------------- cooperative loads ----------------
    {
        const float4* src = (const float4*)gW1;          // rows 0..63
        float4* dst = (float4*)sW1a;
        for (int i = tid; i < 4096; i += NTHREADS) dst[i] = src[i];
    }
    {
        const float4* src = (const float4*)(gW1 + 64 * HID);  // rows 64..95 -> sW2 region
        float4* dst = (float4*)sW2;
        for (int i = tid; i < 2048; i += NTHREADS) dst[i] = src[i];
    }
    if (tid < 64)  ((float4*)sB1)[tid] = ((const float4*)gb1)[tid];
    if (tid < 8)   sDel[tid] = gT[sb * (BLK_T + 1) + tid + 1] - gT[sb * (BLK_T + 1) + tid];
    if (tid < 128) ((float4*)sPhi)[tid] =
        ((const float4*)(gPhi + ((size_t)sb * N_DIM + node0) * P_DIM))[tid];
    {
        const int n   = tid >> 4;
        const int col = (tid & 15) * 4;
        const size_t goff = ((size_t)sb * N_DIM + node0 + n) * D_DIM + col;
        *(float4*)(sX + n * XPAD + col) = *(const float4*)(gS + goff);
        float4 bv  = *(const float4*)(gB + goff);
        float4 b2v = *(const float4*)(gb2 + col);
        bv.x += b2v.x; bv.y += b2v.y; bv.z += b2v.z; bv.w += b2v.w;
        *(float4*)(sBB + n * XPAD + col) = bv;
    }
    __syncthreads();

    // ---------------- precompute c = Phi @ W1p + b1 ----------------
    {
        const int nb = (tid >> 6) * 4;
        const int hc = (tid & 63) * 4;
        float acc[4][4];
        float4 bv = *(const float4*)(sB1 + hc);
        #pragma unroll
        for (int nr = 0; nr < 4; nr++) {
            acc[nr][0] = bv.x; acc[nr][1] = bv.y; acc[nr][2] = bv.z; acc[nr][3] = bv.w;
        }
        #pragma unroll 4
        for (int q = 0; q < P_DIM; q += 4) {
            float4 pv[4];
            #pragma unroll
            for (int nr = 0; nr < 4; nr++)
                pv[nr] = *(const float4*)(sPhi + (nb + nr) * P_DIM + q);
            #pragma unroll
            for (int j = 0; j < 4; j++) {
                float4 wv = *(const float4*)(sW2 + (q + j) * HID + hc);  // W1p rows
                #pragma unroll
                for (int nr = 0; nr < 4; nr++) {
                    float p = comp4(pv[nr], j);
                    acc[nr][0] += p * wv.x; acc[nr][1] += p * wv.y;
                    acc[nr][2] += p * wv.z; acc[nr][3] += p * wv.w;
                }
            }
        }
        #pragma unroll
        for (int nr = 0; nr < 4; nr++)
            *(float4*)(sC + (nb + nr) * CPAD + hc) =
                make_float4(acc[nr][0], acc[nr][1], acc[nr][2], acc[nr][3]);
    }
    __syncthreads();

    // load real W2
    {
        const float4* src = (const float4*)gW2;
        float4* dst = (float4*)sW2;
        for (int i = tid; i < 4096; i += NTHREADS) dst[i] = src[i];
    }
    __syncthreads();

    // ---------------- time march ----------------
    const int   n_ew = tid >> 4;
    const int   c_ew = (tid & 15) * 4;
    const int   ew   = n_ew * XPAD + c_ew;
    const float DT   = 1.0f / NSTEPS;      // 0.5
    const float HDT  = 0.5f * DT;          // 0.25
    const float DT6  = DT / 6.0f;

    for (int k = 0; k < BLK_T; k++) {
        const float dlt = sDel[k];
        for (int st = 0; st < NSTEPS; st++) {
            float4 accR;
            // k1
            dyn_eval(sX, sH, sW1a, sC, sW2, sBB, sK, dlt, tid);
            {
                float4 kv = *(const float4*)(sK + ew);
                float4 xv = *(const float4*)(sX + ew);
                accR = kv;
                float4 yv;
                yv.x = xv.x + HDT * kv.x; yv.y = xv.y + HDT * kv.y;
                yv.z = xv.z + HDT * kv.z; yv.w = xv.w + HDT * kv.w;
                *(float4*)(sY + ew) = yv;
            }
            __syncthreads();
            // k2
            dyn_eval(sY, sH, sW1a, sC, sW2, sBB, sK, dlt, tid);
            {
                float4 kv = *(const float4*)(sK + ew);
                float4 xv = *(const float4*)(sX + ew);
                accR.x += 2.f * kv.x; accR.y += 2.f * kv.y;
                accR.z += 2.f * kv.z; accR.w += 2.f * kv.w;
                float4 yv;
                yv.x = xv.x + HDT * kv.x; yv.y = xv.y + HDT * kv.y;
                yv.z = xv.z + HDT * kv.z; yv.w = xv.w + HDT * kv.w;
                *(float4*)(sY + ew) = yv;
            }
            __syncthreads();
            // k3
            dyn_eval(sY, sH, sW1a, sC, sW2, sBB, sK, dlt, tid);
            {
                float4 kv = *(const float4*)(sK + ew);
                float4 xv = *(const float4*)(sX + ew);
                accR.x += 2.f * kv.x; accR.y += 2.f * kv.y;
                accR.z += 2.f * kv.z; accR.w += 2.f * kv.w;
                float4 yv;
                yv.x = xv.x + DT * kv.x; yv.y = xv.y + DT * kv.y;
                yv.z = xv.z + DT * kv.z; yv.w = xv.w + DT * kv.w;
                *(float4*)(sY + ew) = yv;
            }
            __syncthreads();
            // k4 + update
            dyn_eval(sY, sH, sW1a, sC, sW2, sBB, sK, dlt, tid);
            {
                float4 kv = *(const float4*)(sK + ew);
                float4 xv = *(const float4*)(sX + ew);
                accR.x += kv.x; accR.y += kv.y; accR.z += kv.z; accR.w += kv.w;
                xv.x += DT6 * accR.x; xv.y += DT6 * accR.y;
                xv.z += DT6 * accR.z; xv.w += DT6 * accR.w;
                *(float4*)(sX + ew) = xv;
            }
            __syncthreads();
        }
        // write state after this block step
        {
            const size_t base = (size_t)s_i * ((size_t)B_DIM * BLK_T * N_DIM * D_DIM)
                              + (size_t)(b_i * BLK_T + k) * ((size_t)N_DIM * D_DIM)
                              + (size_t)node0 * D_DIM;
            *(float4*)(gOut + base + (size_t)tid * 4) = *(const float4*)(sX + ew);
        }
    }
}

extern "C" void kernel_launch(void* const* d_in, const int* in_sizes, int n_in,
                              void* d_out, int out_size) {
    (void)in_sizes; (void)n_in; (void)out_size;
    const float* s   = (const float*)d_in[0];
    const float* t   = (const float*)d_in[1];
    const float* Phi = (const float*)d_in[2];
    const float* b   = (const float*)d_in[3];
    const float* W1  = (const float*)d_in[4];
    const float* b1  = (const float*)d_in[5];
    const float* W2  = (const float*)d_in[6];
    const float* b2  = (const float*)d_in[7];
    float* out = (float*)d_out;

    const int smem_bytes = SMEM_FLOATS * (int)sizeof(float);
    cudaFuncSetAttribute(ode_fused_kernel,
                         cudaFuncAttributeMaxDynamicSharedMemorySize, smem_bytes);
    const int n_ctas = (S_DIM * B_DIM) * (N_DIM / TN);   // 2048
    ode_fused_kernel<<<n_ctas, NTHREADS, smem_bytes>>>(s, t, Phi, b, W1, b1, W2, b2, out);
}

// round 3
// speedup vs baseline: 1.1341x; 1.1341x over previous
#include <cuda_runtime.h>

// ---------------- problem constants ----------------
#define S_DIM   2
#define B_DIM   8
#define N_DIM   2048
#define D_DIM   64
#define P_DIM   32
#define BLK_T   8
#define HID     256

#define TN       32      // nodes per CTA
#define NTHREADS 512
#define NP       36      // node-stride (floats) for float4-accessed transposed arrays
#define NPB      34      // node-stride for b64-only transposed arrays

// ---------------- shared layout (floats) ----------------
#define OFF_W1A 0                       // 64*256   = 16384
#define OFF_W2  16384                   // 256*64   = 16384
#define OFF_CT  32768                   // 256*NPB  = 8704
#define OFF_HT  (32768 + 8704)          // 41472 : 256*NP = 9216 (overlay: W1p / splitK scratch)
#define OFF_XT  (41472 + 9216)          // 50688 : 64*NP = 2304
#define OFF_BT  (50688 + 2304)          // 52992 : 64*NP = 2304 (overlay: PhiT + b1 during init)
#define OFF_BBT (52992 + 2304)          // 55296 : 64*NPB = 2176
#define OFF_DEL (55296 + 2176)          // 57472 : 8
#define SMEM_FLOATS 57480               // 229,920 bytes

typedef unsigned long long u64;

__device__ __forceinline__ void ffma2(u64 &d, u64 a, u64 b) {
    asm("fma.rn.f32x2 %0, %1, %2, %0;" : "+l"(d) : "l"(a), "l"(b));
}
__device__ __forceinline__ u64 pk2(float lo, float hi) {
    u64 r; asm("mov.b64 %0, {%1, %2};" : "=l"(r) : "f"(lo), "f"(hi)); return r;
}
__device__ __forceinline__ float2 up2(u64 v) {
    float2 r; asm("mov.b64 {%0, %1}, %2;" : "=f"(r.x), "=f"(r.y) : "l"(v)); return r;
}
__device__ __forceinline__ float tanh_fast(float x) {
    float u = __expf(-2.0f * fabsf(x));
    float t = __fdividef(1.0f - u, 1.0f + u);
    return copysignf(t, x);
}

extern __shared__ float smem[];

// One dynamics evaluation for the CTA's 32 nodes.
// Input state sIn is transposed [64 feat][NP]. Returns per-thread float4:
//   [ (n0,d0), (n1,d0), (n0,d1), (n1,d1) ] raw MLP output (before +bb, *dlt)
// for nodes n0=2*rp, n1=2*rp+1 and cols d0=2*dgc, d1=2*dgc+1 (rp=tid>>5, dgc=tid&31).
__device__ __forceinline__ float4 dyn_core(const float* __restrict__ sIn, int tid)
{
    float* sW1a = smem + OFF_W1A;
    float* sW2  = smem + OFF_W2;
    float* sCT  = smem + OFF_CT;
    float* sHT  = smem + OFF_HT;

    // ---------- GEMM1: h = tanh(x @ W1a + c), pairs over nodes ----------
    {
        const int nb   = (tid >> 7) * 8;     // 8 nodes = 4 pairs
        const int col0 = (tid & 127) * 2;    // 2 hidden cols
        u64 acc[4][2];
        #pragma unroll
        for (int c = 0; c < 2; c++)
            #pragma unroll
            for (int p = 0; p < 4; p++)
                acc[p][c] = *(const u64*)(sCT + (col0 + c) * NPB + nb + 2 * p);

        #pragma unroll 8
        for (int f = 0; f < D_DIM; f++) {
            ulonglong2 Y0 = *(const ulonglong2*)(sIn + f * NP + nb);
            ulonglong2 Y1 = *(const ulonglong2*)(sIn + f * NP + nb + 4);
            float2 w = *(const float2*)(sW1a + f * HID + col0);
            u64 wx = pk2(w.x, w.x), wy = pk2(w.y, w.y);
            ffma2(acc[0][0], Y0.x, wx); ffma2(acc[0][1], Y0.x, wy);
            ffma2(acc[1][0], Y0.y, wx); ffma2(acc[1][1], Y0.y, wy);
            ffma2(acc[2][0], Y1.x, wx); ffma2(acc[2][1], Y1.x, wy);
            ffma2(acc[3][0], Y1.y, wx); ffma2(acc[3][1], Y1.y, wy);
        }
        #pragma unroll
        for (int c = 0; c < 2; c++) {
            float2 a0 = up2(acc[0][c]), a1 = up2(acc[1][c]);
            float2 a2 = up2(acc[2][c]), a3 = up2(acc[3][c]);
            float4 v0 = make_float4(tanh_fast(a0.x), tanh_fast(a0.y),
                                    tanh_fast(a1.x), tanh_fast(a1.y));
            float4 v1 = make_float4(tanh_fast(a2.x), tanh_fast(a2.y),
                                    tanh_fast(a3.x), tanh_fast(a3.y));
            *(float4*)(sHT + (col0 + c) * NP + nb)     = v0;
            *(float4*)(sHT + (col0 + c) * NP + nb + 4) = v1;
        }
    }
    __syncthreads();   // S1: h visible

    // ---------- GEMM2: k_raw = h @ W2, split-K=4, pairs over nodes ----------
    const int ks  = tid >> 7;         // k-slice
    const int pg  = (tid >> 5) & 3;   // node-pair group (4 pairs)
    const int dgc = tid & 31;         // col-pair
    u64 pacc[4][2];
    {
        const int nb2 = pg * 8;
        const int c0  = dgc * 2;
        const int k0  = ks * 64;
        #pragma unroll
        for (int p = 0; p < 4; p++) { pacc[p][0] = 0ULL; pacc[p][1] = 0ULL; }
        #pragma unroll 8
        for (int kk = 0; kk < 64; kk++) {
            const int k = k0 + kk;
            ulonglong2 H0 = *(const ulonglong2*)(sHT + k * NP + nb2);
            ulonglong2 H1 = *(const ulonglong2*)(sHT + k * NP + nb2 + 4);
            float2 w = *(const float2*)(sW2 + k * D_DIM + c0);
            u64 wx = pk2(w.x, w.x), wy = pk2(w.y, w.y);
            ffma2(pacc[0][0], H0.x, wx); ffma2(pacc[0][1], H0.x, wy);
            ffma2(pacc[1][0], H0.y, wx); ffma2(pacc[1][1], H0.y, wy);
            ffma2(pacc[2][0], H1.x, wx); ffma2(pacc[2][1], H1.x, wy);
            ffma2(pacc[3][0], H1.y, wx); ffma2(pacc[3][1], H1.y, wy);
        }
    }
    __syncthreads();   // S2: sHT reads done, safe to overlay scratch
    {
        float* scr = sHT;   // [4 slices][16 pairs][132]
        #pragma unroll
        for (int p = 0; p < 4; p++) {
            ulonglong2 v; v.x = pacc[p][0]; v.y = pacc[p][1];
            *(ulonglong2*)(scr + ks * 2112 + (pg * 4 + p) * 132 + dgc * 4) = v;
        }
    }
    __syncthreads();   // S3: partials visible

    const int rp = tid >> 5;
    const float* scr = sHT;
    float4 sum = *(const float4*)(scr + rp * 132 + dgc * 4);
    #pragma unroll
    for (int s = 1; s < 4; s++) {
        float4 v = *(const float4*)(scr + s * 2112 + rp * 132 + dgc * 4);
        sum.x += v.x; sum.y += v.y; sum.z += v.z; sum.w += v.w;
    }
    return sum;
}

__global__ void __launch_bounds__(NTHREADS, 1)
ode_kernel(const float* __restrict__ gS,  const float* __restrict__ gT,
           const float* __restrict__ gPhi, const float* __restrict__ gB,
           const float* __restrict__ gW1, const float* __restrict__ gb1,
           const float* __restrict__ gW2, const float* __restrict__ gb2,
           float* __restrict__ gOut)
{
    const int tid   = threadIdx.x;
    const int sb    = blockIdx.x >> 6;       // 16 (s,b) pairs
    const int tile  = blockIdx.x & 63;       // 64 tiles of 32 nodes
    const int node0 = tile * TN;
    const int s_i   = sb >> 3, b_i = sb & 7;

    float* sW1a = smem + OFF_W1A;
    float* sW2  = smem + OFF_W2;
    float* sCT  = smem + OFF_CT;
    float* sHT  = smem + OFF_HT;
    float* sXT  = smem + OFF_XT;
    float* sBT  = smem + OFF_BT;
    float* sBBT = smem + OFF_BBT;
    float* sDel = smem + OFF_DEL;

    // ---------------- init loads ----------------
    {
        const float4* w1  = (const float4*)gW1;
        for (int i = tid; i < 4096; i += NTHREADS) ((float4*)sW1a)[i] = w1[i];
        const float4* w1p = (const float4*)(gW1 + 64 * HID);     // Phi-rows of W1
        for (int i = tid; i < 2048; i += NTHREADS) ((float4*)sHT)[i] = w1p[i];
        const float4* w2  = (const float4*)gW2;
        for (int i = tid; i < 4096; i += NTHREADS) ((float4*)sW2)[i] = w2[i];
    }
    {
        const size_t base = ((size_t)sb * N_DIM + node0) * D_DIM;
        for (int i = tid; i < TN * D_DIM; i += NTHREADS) {
            int node = i >> 6, dd = i & 63;
            sXT[dd * NP + node]   = gS[base + i];
            sBBT[dd * NPB + node] = gB[base + i] + gb2[dd];
        }
        const size_t pbase = ((size_t)sb * N_DIM + node0) * P_DIM;
        for (int i = tid; i < TN * P_DIM; i += NTHREADS) {
            int node = i >> 5, q = i & 31;
            sBT[q * NP + node] = gPhi[pbase + i];            // PhiT overlay
        }
        if (tid < HID)  sBT[32 * NP + tid] = gb1[tid];       // b1 overlay
        if (tid < BLK_T) sDel[tid] = gT[sb * (BLK_T + 1) + tid + 1]
                                   - gT[sb * (BLK_T + 1) + tid];
    }
    __syncthreads();

    // ---------------- c = Phi @ W1p + b1  (into sCT, pairs over nodes) --------
    {
        const int nb   = (tid >> 7) * 8;
        const int col0 = (tid & 127) * 2;
        const float* sPhiT = sBT;
        const float* sB1   = sBT + 32 * NP;
        float2 bw = *(const float2*)(sB1 + col0);
        u64 bx = pk2(bw.x, bw.x), by = pk2(bw.y, bw.y);
        u64 acc[4][2];
        #pragma unroll
        for (int p = 0; p < 4; p++) { acc[p][0] = bx; acc[p][1] = by; }
        #pragma unroll 8
        for (int q = 0; q < P_DIM; q++) {
            ulonglong2 Y0 = *(const ulonglong2*)(sPhiT + q * NP + nb);
            ulonglong2 Y1 = *(const ulonglong2*)(sPhiT + q * NP + nb + 4);
            float2 w = *(const float2*)(sHT + q * HID + col0);   // W1p
            u64 wx = pk2(w.x, w.x), wy = pk2(w.y, w.y);
            ffma2(acc[0][0], Y0.x, wx); ffma2(acc[0][1], Y0.x, wy);
            ffma2(acc[1][0], Y0.y, wx); ffma2(acc[1][1], Y0.y, wy);
            ffma2(acc[2][0], Y1.x, wx); ffma2(acc[2][1], Y1.x, wy);
            ffma2(acc[3][0], Y1.y, wx); ffma2(acc[3][1], Y1.y, wy);
        }
        #pragma unroll
        for (int c = 0; c < 2; c++)
            #pragma unroll
            for (int p = 0; p < 4; p++)
                *(u64*)(sCT + (col0 + c) * NPB + nb + 2 * p) = acc[p][c];
    }
    __syncthreads();

    // ---------------- time march ----------------
    const int rp  = tid >> 5;
    const int dgc = tid & 31;
    const int xa0 = (2 * dgc) * NP + 2 * rp;       // sXT/sBT addr, col d0
    const int xa1 = xa0 + NP;                      // col d1
    float2 bbA = *(const float2*)(sBBT + (2 * dgc) * NPB + 2 * rp);
    float2 bbB = *(const float2*)(sBBT + (2 * dgc + 1) * NPB + 2 * rp);

    for (int kb = 0; kb < BLK_T; kb++) {
        const float dlt = sDel[kb];
        #pragma unroll
        for (int st = 0; st < 2; st++) {
            float4 accR;
            // ---- RK4 stage 0 ----
            {
                float4 s4 = dyn_core(sXT, tid);
                float k0 = (s4.x + bbA.x) * dlt, k1 = (s4.y + bbA.y) * dlt;
                float k2 = (s4.z + bbB.x) * dlt, k3 = (s4.w + bbB.y) * dlt;
                accR = make_float4(k0, k1, k2, k3);
                float2 xA = *(const float2*)(sXT + xa0);
                float2 xB = *(const float2*)(sXT + xa1);
                *(float2*)(sBT + xa0) = make_float2(xA.x + 0.25f * k0, xA.y + 0.25f * k1);
                *(float2*)(sBT + xa1) = make_float2(xB.x + 0.25f * k2, xB.y + 0.25f * k3);
                __syncthreads();
            }
            // ---- stage 1 ----
            {
                float4 s4 = dyn_core(sBT, tid);
                float k0 = (s4.x + bbA.x) * dlt, k1 = (s4.y + bbA.y) * dlt;
                float k2 = (s4.z + bbB.x) * dlt, k3 = (s4.w + bbB.y) * dlt;
                accR.x += 2.f * k0; accR.y += 2.f * k1;
                accR.z += 2.f * k2; accR.w += 2.f * k3;
                float2 xA = *(const float2*)(sXT + xa0);
                float2 xB = *(const float2*)(sXT + xa1);
                *(float2*)(sBT + xa0) = make_float2(xA.x + 0.25f * k0, xA.y + 0.25f * k1);
                *(float2*)(sBT + xa1) = make_float2(xB.x + 0.25f * k2, xB.y + 0.25f * k3);
                __syncthreads();
            }
            // ---- stage 2 ----
            {
                float4 s4 = dyn_core(sBT, tid);
                float k0 = (s4.x + bbA.x) * dlt, k1 = (s4.y + bbA.y) * dlt;
                float k2 = (s4.z + bbB.x) * dlt, k3 = (s4.w + bbB.y) * dlt;
                accR.x += 2.f * k0; accR.y += 2.f * k1;
                accR.z += 2.f * k2; accR.w += 2.f * k3;
                float2 xA = *(const float2*)(sXT + xa0);
                float2 xB = *(const float2*)(sXT + xa1);
                *(float2*)(sBT + xa0) = make_float2(xA.x + 0.5f * k0, xA.y + 0.5f * k1);
                *(float2*)(sBT + xa1) = make_float2(xB.x + 0.5f * k2, xB.y + 0.5f * k3);
                __syncthreads();
            }
            // ---- stage 3 + state update (+ output on st==1) ----
            {
                float4 s4 = dyn_core(sBT, tid);
                float k0 = (s4.x + bbA.x) * dlt, k1 = (s4.y + bbA.y) * dlt;
                float k2 = (s4.z + bbB.x) * dlt, k3 = (s4.w + bbB.y) * dlt;
                accR.x += k0; accR.y += k1; accR.z += k2; accR.w += k3;
                float2 xA = *(const float2*)(sXT + xa0);
                float2 xB = *(const float2*)(sXT + xa1);
                const float c6 = 1.0f / 12.0f;   // dt/6 with dt = 0.5
                xA.x += c6 * accR.x; xA.y += c6 * accR.y;
                xB.x += c6 * accR.z; xB.y += c6 * accR.w;
                *(float2*)(sXT + xa0) = xA;
                *(float2*)(sXT + xa1) = xB;
                if (st == 1) {
                    const size_t obase =
                        ((size_t)((s_i * B_DIM + b_i) * BLK_T + kb) * N_DIM + node0) * D_DIM;
                    *(float2*)(gOut + obase + (size_t)(2 * rp) * D_DIM + 2 * dgc)
                        = make_float2(xA.x, xB.x);
                    *(float2*)(gOut + obase + (size_t)(2 * rp + 1) * D_DIM + 2 * dgc)
                        = make_float2(xA.y, xB.y);
                }
                __syncthreads();
            }
        }
    }
}

extern "C" void kernel_launch(void* const* d_in, const int* in_sizes, int n_in,
                              void* d_out, int out_size) {
    (void)in_sizes; (void)n_in; (void)out_size;
    const float* s   = (const float*)d_in[0];
    const float* t   = (const float*)d_in[1];
    const float* Phi = (const float*)d_in[2];
    const float* b   = (const float*)d_in[3];
    const float* W1  = (const float*)d_in[4];
    const float* b1  = (const float*)d_in[5];
    const float* W2  = (const float*)d_in[6];
    const float* b2  = (const float*)d_in[7];
    float* out = (float*)d_out;

    const int smem_bytes = SMEM_FLOATS * (int)sizeof(float);   // 229,920 B
    cudaFuncSetAttribute(ode_kernel,
                         cudaFuncAttributeMaxDynamicSharedMemorySize, smem_bytes);
    const int n_ctas = (S_DIM * B_DIM) * (N_DIM / TN);         // 1024
    ode_kernel<<<n_ctas, NTHREADS, smem_bytes>>>(s, t, Phi, b, W1, b1, W2, b2, out);
}